// round 2
// baseline (speedup 1.0000x reference)
#include <cuda_runtime.h>
#include <cstdint>

// Problem constants (fixed by the reference: B=64, C=128, H=W=64)
#define BB 64
#define CC 128
#define MM 4096
#define KSPLIT 8
#define KC (MM / KSPLIT)   // 512

// scratch for per-row means (allocation-free rule: __device__ global)
__device__ float g_mu[BB * CC];

// ---------------------------------------------------------------------------
// Kernel 1: per-(b,c) mean over M=4096 spatial elements
// ---------------------------------------------------------------------------
__global__ void mean_kernel(const float* __restrict__ x) {
    const int row = blockIdx.x;                    // b*C + c, 0..8191
    const float4* p = reinterpret_cast<const float4*>(x + (size_t)row * MM);
    float s = 0.0f;
    for (int i = threadIdx.x; i < MM / 4; i += blockDim.x) {
        float4 v = p[i];
        s += (v.x + v.y) + (v.z + v.w);
    }
    // warp reduce
    #pragma unroll
    for (int o = 16; o > 0; o >>= 1) s += __shfl_xor_sync(0xffffffffu, s, o);
    __shared__ float ws[8];
    if ((threadIdx.x & 31) == 0) ws[threadIdx.x >> 5] = s;
    __syncthreads();
    if (threadIdx.x < 8) {
        s = ws[threadIdx.x];
        #pragma unroll
        for (int o = 4; o > 0; o >>= 1) s += __shfl_xor_sync(0xffu, s, o);
        if (threadIdx.x == 0) g_mu[row] = s * (1.0f / MM);
    }
}

// ---------------------------------------------------------------------------
// Kernel 2: initialize out[b][c][d] = -mu[b][c] * mu[b][d]
// (also serves as the required init of the poisoned output buffer)
// ---------------------------------------------------------------------------
__global__ void init_kernel(float* __restrict__ out) {
    const int idx = blockIdx.x * blockDim.x + threadIdx.x;   // over B*C*C = 1M
    const int b = idx >> 14;
    const int c = (idx >> 7) & (CC - 1);
    const int d = idx & (CC - 1);
    out[idx] = -g_mu[b * CC + c] * g_mu[b * CC + d];
}

// ---------------------------------------------------------------------------
// Kernel 3: split-K SYRK: out[b] += (1/M) * x_chunk @ x_chunk^T
// grid = (KSPLIT, B), 256 threads, 128x128 tile, 8x8 microtile per thread.
// Inner product uses packed dual-fp32 FMA (fma.rn.f32x2) for 2x FFMA rate.
// ---------------------------------------------------------------------------
__global__ void __launch_bounds__(256) syrk_kernel(const float* __restrict__ x,
                                                   float* __restrict__ out) {
    const int b  = blockIdx.y;
    const int ks = blockIdx.x;
    const float* xb = x + (size_t)b * CC * MM + ks * KC;

    __shared__ float s[16][CC + 4];   // k-major, padded (132 floats/row)

    const int tid = threadIdx.x;
    const int tx = tid & 15;          // output column group
    const int ty = tid >> 4;          // output row group

    // 8x8 fp32 accumulators held as 8x4 packed f32x2
    unsigned long long acc[8][4];
    #pragma unroll
    for (int i = 0; i < 8; i++)
        #pragma unroll
        for (int j = 0; j < 4; j++) acc[i][j] = 0ull;

    for (int k0 = 0; k0 < KC; k0 += 16) {
        // stage 128 rows x 16 k into smem (transposed to k-major)
        #pragma unroll
        for (int l = 0; l < 2; l++) {
            int idx = tid + l * 256;       // 0..511
            int row = idx >> 2;            // 0..127
            int seg = idx & 3;             // 0..3 (4 floats each)
            float4 v = *reinterpret_cast<const float4*>(
                xb + (size_t)row * MM + k0 + seg * 4);
            s[seg * 4 + 0][row] = v.x;
            s[seg * 4 + 1][row] = v.y;
            s[seg * 4 + 2][row] = v.z;
            s[seg * 4 + 3][row] = v.w;
        }
        __syncthreads();

        #pragma unroll
        for (int k = 0; k < 16; k++) {
            // a: 8 row values (ty), b: 8 col values (tx) as 4 packed pairs
            float a[8];
            *reinterpret_cast<float4*>(a)     = *reinterpret_cast<const float4*>(&s[k][ty * 8]);
            *reinterpret_cast<float4*>(a + 4) = *reinterpret_cast<const float4*>(&s[k][ty * 8 + 4]);

            unsigned long long b2[4];
            {
                ulonglong2 t0 = *reinterpret_cast<const ulonglong2*>(&s[k][tx * 8]);
                b2[0] = t0.x; b2[1] = t0.y;
                ulonglong2 t1 = *reinterpret_cast<const ulonglong2*>(&s[k][tx * 8 + 4]);
                b2[2] = t1.x; b2[3] = t1.y;
            }

            #pragma unroll
            for (int i = 0; i < 8; i++) {
                unsigned long long a2;
                unsigned int au = __float_as_uint(a[i]);
                asm("mov.b64 %0, {%1, %1};" : "=l"(a2) : "r"(au));
                #pragma unroll
                for (int j = 0; j < 4; j++) {
                    asm("fma.rn.f32x2 %0, %1, %2, %0;"
                        : "+l"(acc[i][j]) : "l"(a2), "l"(b2[j]));
                }
            }
        }
        __syncthreads();
    }

    // epilogue: accumulate scaled partials into global output
    float* ob = out + (size_t)b * CC * CC;
    const float scale = 1.0f / MM;
    #pragma unroll
    for (int i = 0; i < 8; i++) {
        const int r = ty * 8 + i;
        #pragma unroll
        for (int j = 0; j < 4; j++) {
            float2 v = *reinterpret_cast<float2*>(&acc[i][j]);
            atomicAdd(&ob[r * CC + tx * 8 + 2 * j],     v.x * scale);
            atomicAdd(&ob[r * CC + tx * 8 + 2 * j + 1], v.y * scale);
        }
    }
}

// ---------------------------------------------------------------------------
extern "C" void kernel_launch(void* const* d_in, const int* in_sizes, int n_in,
                              void* d_out, int out_size) {
    const float* x = (const float*)d_in[0];
    float* out = (float*)d_out;

    mean_kernel<<<BB * CC, 256>>>(x);
    init_kernel<<<(BB * CC * CC) / 256, 256>>>(out);
    dim3 grid(KSPLIT, BB);
    syrk_kernel<<<grid, 256>>>(x, out);
}

// round 5
// speedup vs baseline: 3.0765x; 3.0765x over previous
#include <cuda_runtime.h>
#include <cstdint>

// Problem constants: B=64, C=128, M=H*W=4096, fp32 in/out
#define BB 64
#define CC 128
#define MM 4096
#define KS 2                   // split-K across CTAs
#define KCHUNK (MM / KS)       // 2048
#define KTILE 32               // bf16 k per stage
#define NSTAGE (KCHUNK / KTILE) // 64
#define PITCH 80               // smem row pitch bytes (64B data + 16B pad)
#define TILEB (CC * PITCH)     // 10240 bytes per bf16 tile

// ---------------- scratch (__device__ globals; no allocs allowed) ----------
__device__ float g_sum[BB * CC];                 // per-(b,c) row sums
__device__ float g_part[KS * BB * CC * CC];      // split-K partial Grams

// ---------------- helpers ---------------------------------------------------
__device__ __forceinline__ uint32_t smem_u32(const void* p) {
    uint32_t a;
    asm("{ .reg .u64 t; cvta.to.shared.u64 t, %1; cvt.u32.u64 %0, t; }"
        : "=r"(a) : "l"(p));
    return a;
}
__device__ __forceinline__ void ldsm_x4(uint32_t& r0, uint32_t& r1,
                                        uint32_t& r2, uint32_t& r3, uint32_t a) {
    asm volatile("ldmatrix.sync.aligned.m8n8.x4.shared.b16 {%0,%1,%2,%3}, [%4];"
                 : "=r"(r0), "=r"(r1), "=r"(r2), "=r"(r3) : "r"(a));
}
__device__ __forceinline__ void ldsm_x2(uint32_t& r0, uint32_t& r1, uint32_t a) {
    asm volatile("ldmatrix.sync.aligned.m8n8.x2.shared.b16 {%0,%1}, [%2];"
                 : "=r"(r0), "=r"(r1) : "r"(a));
}
__device__ __forceinline__ void mma_bf16(float* d, const uint32_t* a,
                                         uint32_t b0, uint32_t b1) {
    asm volatile(
        "mma.sync.aligned.m16n8k16.row.col.f32.bf16.bf16.f32 "
        "{%0,%1,%2,%3}, {%4,%5,%6,%7}, {%8,%9}, {%0,%1,%2,%3};"
        : "+f"(d[0]), "+f"(d[1]), "+f"(d[2]), "+f"(d[3])
        : "r"(a[0]), "r"(a[1]), "r"(a[2]), "r"(a[3]), "r"(b0), "r"(b1));
}

// ---------------------------------------------------------------------------
__global__ void zero_sums() {
    int i = blockIdx.x * blockDim.x + threadIdx.x;
    if (i < BB * CC) g_sum[i] = 0.0f;
}

// ---------------------------------------------------------------------------
// SYRK via bf16-split mma.sync. grid = (KS, BB), 256 threads.
// smem: per double-buffer: hi tile [128 x 32 bf16, pitch 80] + lo tile.
// ---------------------------------------------------------------------------
__global__ void __launch_bounds__(256, 1) syrk_mma(const float* __restrict__ x) {
    __shared__ __align__(128) uint8_t smem[2][2 * TILEB];

    const int tid = threadIdx.x;
    const int wid = tid >> 5;
    const int lid = tid & 31;
    const int b = blockIdx.y;
    const int ks = blockIdx.x;
    const float* xb = x + (size_t)b * CC * MM + ks * KCHUNK;

    const int rw = (wid >> 1) * 32;   // warp row base in 128x128 output
    const int cw = (wid & 1) * 64;    // warp col base

    float acc[2][8][4];
    #pragma unroll
    for (int mb = 0; mb < 2; mb++)
        #pragma unroll
        for (int jb = 0; jb < 8; jb++)
            #pragma unroll
            for (int q = 0; q < 4; q++) acc[mb][jb][q] = 0.0f;

    float rs[4] = {0.f, 0.f, 0.f, 0.f};

    // loader mapping: thread covers rows it*32 + (tid>>3), k-seg (tid&7)*4
    const int lrow = tid >> 3;
    const int kseg = tid & 7;

    // precompute ldmatrix lane offsets (byte offsets inside a tile)
    // A (x4): row = rw + mb*16 + (lid&7) + ((lid>>3)&1)*8 ; kcol8 = (lid>>4)*8
    const uint32_t a_row_off = ((lid & 7) + ((lid >> 3) & 1) * 8) * PITCH
                             + ((lid >> 4) * 8) * 2;
    // B (x2): row = cw + jb*8 + (lid&7) ; kcol8 = ((lid>>3)&1)*8
    const uint32_t b_row_off = (lid & 7) * PITCH + (((lid >> 3) & 1) * 8) * 2;

    float4 v[4];
    #pragma unroll
    for (int it = 0; it < 4; it++)
        v[it] = *reinterpret_cast<const float4*>(
            xb + (size_t)(it * 32 + lrow) * MM + 0 + kseg * 4);

    for (int s = 0; s < NSTAGE; s++) {
        const int buf = s & 1;
        const uint32_t hibase = smem_u32(&smem[buf][0]);
        const uint32_t lobase = hibase + TILEB;

        // convert current regs -> smem tiles, accumulate row sums
        #pragma unroll
        for (int it = 0; it < 4; it++) {
            const int row = it * 32 + lrow;
            const float4 xv = v[it];
            rs[it] += (xv.x + xv.y) + (xv.z + xv.w);
            uint32_t h01, h23, l01, l23;
            asm("cvt.rn.bf16x2.f32 %0, %1, %2;" : "=r"(h01) : "f"(xv.y), "f"(xv.x));
            asm("cvt.rn.bf16x2.f32 %0, %1, %2;" : "=r"(h23) : "f"(xv.w), "f"(xv.z));
            const float hx = __uint_as_float(h01 << 16);
            const float hy = __uint_as_float(h01 & 0xffff0000u);
            const float hz = __uint_as_float(h23 << 16);
            const float hw = __uint_as_float(h23 & 0xffff0000u);
            asm("cvt.rn.bf16x2.f32 %0, %1, %2;" : "=r"(l01) : "f"(xv.y - hy), "f"(xv.x - hx));
            asm("cvt.rn.bf16x2.f32 %0, %1, %2;" : "=r"(l23) : "f"(xv.w - hw), "f"(xv.z - hz));
            const uint32_t off = row * PITCH + kseg * 8;
            asm volatile("st.shared.v2.b32 [%0], {%1,%2};"
                         :: "r"(hibase + off), "r"(h01), "r"(h23));
            asm volatile("st.shared.v2.b32 [%0], {%1,%2};"
                         :: "r"(lobase + off), "r"(l01), "r"(l23));
        }
        __syncthreads();

        // issue next stage's global loads early (latency hidden by MMA work)
        if (s + 1 < NSTAGE) {
            const int k0 = (s + 1) * KTILE;
            #pragma unroll
            for (int it = 0; it < 4; it++)
                v[it] = *reinterpret_cast<const float4*>(
                    xb + (size_t)(it * 32 + lrow) * MM + k0 + kseg * 4);
        }

        // compute: 2 k16 steps on this buffer
        #pragma unroll
        for (int kb = 0; kb < 2; kb++) {
            uint32_t ah[2][4], al[2][4];
            #pragma unroll
            for (int mb = 0; mb < 2; mb++) {
                const uint32_t aoff = (rw + mb * 16) * PITCH + kb * 32 + a_row_off;
                ldsm_x4(ah[mb][0], ah[mb][1], ah[mb][2], ah[mb][3], hibase + aoff);
                ldsm_x4(al[mb][0], al[mb][1], al[mb][2], al[mb][3], lobase + aoff);
            }
            #pragma unroll
            for (int jb = 0; jb < 8; jb++) {
                const uint32_t boff = (cw + jb * 8) * PITCH + kb * 32 + b_row_off;
                uint32_t bh0, bh1, bl0, bl1;
                ldsm_x2(bh0, bh1, hibase + boff);
                ldsm_x2(bl0, bl1, lobase + boff);
                #pragma unroll
                for (int mb = 0; mb < 2; mb++) {
                    mma_bf16(acc[mb][jb], ah[mb], bh0, bh1);  // hi*hi
                    mma_bf16(acc[mb][jb], ah[mb], bl0, bl1);  // hi*lo
                    mma_bf16(acc[mb][jb], al[mb], bh0, bh1);  // lo*hi
                }
            }
        }
        __syncthreads();
    }

    // row-sum reduction: 8 lanes (same l>>3 group) share a row
    #pragma unroll
    for (int it = 0; it < 4; it++) {
        float vv = rs[it];
        vv += __shfl_xor_sync(0xffffffffu, vv, 4);
        vv += __shfl_xor_sync(0xffffffffu, vv, 2);
        vv += __shfl_xor_sync(0xffffffffu, vv, 1);
        if ((lid & 7) == 0)
            atomicAdd(&g_sum[b * CC + it * 32 + lrow], vv);
    }

    // epilogue: write partial Gram
    float* dst = g_part + (size_t)(ks * BB + b) * (CC * CC);
    const int g = lid >> 2;
    const int tg = lid & 3;
    #pragma unroll
    for (int mb = 0; mb < 2; mb++) {
        #pragma unroll
        for (int jb = 0; jb < 8; jb++) {
            const int row = rw + mb * 16 + g;
            const int col = cw + jb * 8 + tg * 2;
            *reinterpret_cast<float2*>(&dst[(size_t)row * CC + col]) =
                make_float2(acc[mb][jb][0], acc[mb][jb][1]);
            *reinterpret_cast<float2*>(&dst[(size_t)(row + 8) * CC + col]) =
                make_float2(acc[mb][jb][2], acc[mb][jb][3]);
        }
    }
}

// ---------------------------------------------------------------------------
// out[b][c][d] = (part0 + part1)/M - mu_c * mu_d
__global__ void finalize(float* __restrict__ out) {
    const int i = blockIdx.x * blockDim.x + threadIdx.x;    // float4 index
    const int base = i * 4;
    const int b = base >> 14;
    const int c = (base >> 7) & (CC - 1);
    const int d0 = base & (CC - 1);
    const float inv = 1.0f / (float)MM;

    const float muc = g_sum[b * CC + c] * inv;
    const float m0 = g_sum[b * CC + d0 + 0] * inv;
    const float m1 = g_sum[b * CC + d0 + 1] * inv;
    const float m2 = g_sum[b * CC + d0 + 2] * inv;
    const float m3 = g_sum[b * CC + d0 + 3] * inv;

    const float4 p0 = reinterpret_cast<const float4*>(g_part)[i];
    const float4 p1 = reinterpret_cast<const float4*>(g_part)[BB * CC * CC / 4 + i];

    float4 o;
    o.x = (p0.x + p1.x) * inv - muc * m0;
    o.y = (p0.y + p1.y) * inv - muc * m1;
    o.z = (p0.z + p1.z) * inv - muc * m2;
    o.w = (p0.w + p1.w) * inv - muc * m3;
    reinterpret_cast<float4*>(out)[i] = o;
}

// ---------------------------------------------------------------------------
extern "C" void kernel_launch(void* const* d_in, const int* in_sizes, int n_in,
                              void* d_out, int out_size) {
    const float* x = (const float*)d_in[0];
    float* out = (float*)d_out;

    zero_sums<<<32, 256>>>();
    dim3 grid(KS, BB);
    syrk_mma<<<grid, 256>>>(x);
    finalize<<<(BB * CC * CC / 4) / 256, 256>>>(out);
}

// round 6
// speedup vs baseline: 3.5827x; 1.1645x over previous
#include <cuda_runtime.h>
#include <cstdint>

// Problem constants: B=64, C=128, M=H*W=4096, fp32 in/out
#define BB 64
#define CC 128
#define MM 4096
#define KS 2                    // split-K across CTAs
#define KCHUNK (MM / KS)        // 2048
#define KTILE 32                // bf16 k per stage
#define NSTAGE (KCHUNK / KTILE) // 64
#define PITCH 80                // smem row pitch bytes (64B data + 16B pad)
#define TILEB (CC * PITCH)      // 10240 bytes per bf16 tile

// ---------------- scratch (__device__ globals; no allocs allowed) ----------
__device__ float g_sum[KS * BB * CC];            // per-(ks,b,c) row sums
__device__ float g_partP[KS * BB * CC * CC];     // hi*hi^T partials
__device__ float g_partQ[KS * BB * CC * CC];     // hi*lo^T partials

// ---------------- helpers ---------------------------------------------------
__device__ __forceinline__ uint32_t smem_u32(const void* p) {
    uint32_t a;
    asm("{ .reg .u64 t; cvta.to.shared.u64 t, %1; cvt.u32.u64 %0, t; }"
        : "=r"(a) : "l"(p));
    return a;
}
__device__ __forceinline__ void ldsm_x4(uint32_t& r0, uint32_t& r1,
                                        uint32_t& r2, uint32_t& r3, uint32_t a) {
    asm volatile("ldmatrix.sync.aligned.m8n8.x4.shared.b16 {%0,%1,%2,%3}, [%4];"
                 : "=r"(r0), "=r"(r1), "=r"(r2), "=r"(r3) : "r"(a));
}
__device__ __forceinline__ void ldsm_x2(uint32_t& r0, uint32_t& r1, uint32_t a) {
    asm volatile("ldmatrix.sync.aligned.m8n8.x2.shared.b16 {%0,%1}, [%2];"
                 : "=r"(r0), "=r"(r1) : "r"(a));
}
__device__ __forceinline__ void mma_bf16(float* d, const uint32_t* a,
                                         uint32_t b0, uint32_t b1) {
    asm volatile(
        "mma.sync.aligned.m16n8k16.row.col.f32.bf16.bf16.f32 "
        "{%0,%1,%2,%3}, {%4,%5,%6,%7}, {%8,%9}, {%0,%1,%2,%3};"
        : "+f"(d[0]), "+f"(d[1]), "+f"(d[2]), "+f"(d[3])
        : "r"(a[0]), "r"(a[1]), "r"(a[2]), "r"(a[3]), "r"(b0), "r"(b1));
}

// ---------------------------------------------------------------------------
// SYRK via bf16-split mma.sync, two-term (P = hi*hi^T, Q = hi*lo^T).
// grid = (KS, BB), 256 threads. Transpose term Q^T added in finalize.
// ---------------------------------------------------------------------------
__global__ void __launch_bounds__(256, 1) syrk_mma(const float* __restrict__ x) {
    __shared__ __align__(128) uint8_t smem[2][2 * TILEB];

    const int tid = threadIdx.x;
    const int wid = tid >> 5;
    const int lid = tid & 31;
    const int b = blockIdx.y;
    const int ks = blockIdx.x;
    const float* xb = x + (size_t)b * CC * MM + ks * KCHUNK;

    const int rw = (wid >> 1) * 32;   // warp row base in 128x128 output
    const int cw = (wid & 1) * 64;    // warp col base

    float accP[2][8][4], accQ[2][8][4];
    #pragma unroll
    for (int mb = 0; mb < 2; mb++)
        #pragma unroll
        for (int jb = 0; jb < 8; jb++)
            #pragma unroll
            for (int q = 0; q < 4; q++) { accP[mb][jb][q] = 0.0f; accQ[mb][jb][q] = 0.0f; }

    float rs[4] = {0.f, 0.f, 0.f, 0.f};

    // loader mapping: thread covers rows it*32 + (tid>>3), k-seg (tid&7)*4
    const int lrow = tid >> 3;
    const int kseg = tid & 7;

    // ldmatrix lane byte-offsets inside a tile
    const uint32_t a_row_off = ((lid & 7) + ((lid >> 3) & 1) * 8) * PITCH
                             + ((lid >> 4) * 8) * 2;
    const uint32_t b_row_off = (lid & 7) * PITCH + (((lid >> 3) & 1) * 8) * 2;

    float4 v[4];
    #pragma unroll
    for (int it = 0; it < 4; it++)
        v[it] = *reinterpret_cast<const float4*>(
            xb + (size_t)(it * 32 + lrow) * MM + kseg * 4);

    for (int s = 0; s < NSTAGE; s++) {
        const int buf = s & 1;
        const uint32_t hibase = smem_u32(&smem[buf][0]);
        const uint32_t lobase = hibase + TILEB;

        // convert current regs -> smem tiles, accumulate row sums
        #pragma unroll
        for (int it = 0; it < 4; it++) {
            const int row = it * 32 + lrow;
            const float4 xv = v[it];
            rs[it] += (xv.x + xv.y) + (xv.z + xv.w);
            uint32_t h01, h23, l01, l23;
            asm("cvt.rn.bf16x2.f32 %0, %1, %2;" : "=r"(h01) : "f"(xv.y), "f"(xv.x));
            asm("cvt.rn.bf16x2.f32 %0, %1, %2;" : "=r"(h23) : "f"(xv.w), "f"(xv.z));
            const float hx = __uint_as_float(h01 << 16);
            const float hy = __uint_as_float(h01 & 0xffff0000u);
            const float hz = __uint_as_float(h23 << 16);
            const float hw = __uint_as_float(h23 & 0xffff0000u);
            asm("cvt.rn.bf16x2.f32 %0, %1, %2;" : "=r"(l01) : "f"(xv.y - hy), "f"(xv.x - hx));
            asm("cvt.rn.bf16x2.f32 %0, %1, %2;" : "=r"(l23) : "f"(xv.w - hw), "f"(xv.z - hz));
            const uint32_t off = row * PITCH + kseg * 8;
            asm volatile("st.shared.v2.b32 [%0], {%1,%2};"
                         :: "r"(hibase + off), "r"(h01), "r"(h23));
            asm volatile("st.shared.v2.b32 [%0], {%1,%2};"
                         :: "r"(lobase + off), "r"(l01), "r"(l23));
        }
        // Single barrier per stage: also orders compute(s-2) before the store
        // into this buffer (double buffering makes the trailing sync redundant).
        __syncthreads();

        // issue next stage's global loads early (latency hidden by MMA work)
        if (s + 1 < NSTAGE) {
            const int k0 = (s + 1) * KTILE;
            #pragma unroll
            for (int it = 0; it < 4; it++)
                v[it] = *reinterpret_cast<const float4*>(
                    xb + (size_t)(it * 32 + lrow) * MM + k0 + kseg * 4);
        }

        // compute: 2 k16 steps on this buffer; A is always hi
        #pragma unroll
        for (int kb = 0; kb < 2; kb++) {
            uint32_t ah[2][4];
            #pragma unroll
            for (int mb = 0; mb < 2; mb++) {
                const uint32_t aoff = (rw + mb * 16) * PITCH + kb * 32 + a_row_off;
                ldsm_x4(ah[mb][0], ah[mb][1], ah[mb][2], ah[mb][3], hibase + aoff);
            }
            #pragma unroll
            for (int jb = 0; jb < 8; jb++) {
                const uint32_t boff = (cw + jb * 8) * PITCH + kb * 32 + b_row_off;
                uint32_t bh0, bh1, bl0, bl1;
                ldsm_x2(bh0, bh1, hibase + boff);
                ldsm_x2(bl0, bl1, lobase + boff);
                #pragma unroll
                for (int mb = 0; mb < 2; mb++) {
                    mma_bf16(accP[mb][jb], ah[mb], bh0, bh1);  // hi*hi
                    mma_bf16(accQ[mb][jb], ah[mb], bl0, bl1);  // hi*lo
                }
            }
        }
    }

    // row sums: 8 lanes (same tid>>3 group) share a row; plain store per ks
    #pragma unroll
    for (int it = 0; it < 4; it++) {
        float vv = rs[it];
        vv += __shfl_xor_sync(0xffffffffu, vv, 4);
        vv += __shfl_xor_sync(0xffffffffu, vv, 2);
        vv += __shfl_xor_sync(0xffffffffu, vv, 1);
        if ((lid & 7) == 0)
            g_sum[ks * BB * CC + b * CC + it * 32 + lrow] = vv;
    }

    // epilogue: write partial P and Q
    const size_t dsto = (size_t)(ks * BB + b) * (CC * CC);
    float* dP = g_partP + dsto;
    float* dQ = g_partQ + dsto;
    const int g = lid >> 2;
    const int tg = lid & 3;
    #pragma unroll
    for (int mb = 0; mb < 2; mb++) {
        #pragma unroll
        for (int jb = 0; jb < 8; jb++) {
            const int row = rw + mb * 16 + g;
            const int col = cw + jb * 8 + tg * 2;
            *reinterpret_cast<float2*>(&dP[(size_t)row * CC + col]) =
                make_float2(accP[mb][jb][0], accP[mb][jb][1]);
            *reinterpret_cast<float2*>(&dP[(size_t)(row + 8) * CC + col]) =
                make_float2(accP[mb][jb][2], accP[mb][jb][3]);
            *reinterpret_cast<float2*>(&dQ[(size_t)row * CC + col]) =
                make_float2(accQ[mb][jb][0], accQ[mb][jb][1]);
            *reinterpret_cast<float2*>(&dQ[(size_t)(row + 8) * CC + col]) =
                make_float2(accQ[mb][jb][2], accQ[mb][jb][3]);
        }
    }
}

// ---------------------------------------------------------------------------
// out[b][r][c] = (P0+P1 + Q0+Q1 + (Q0+Q1)^T)/M - mu_r * mu_c
// grid = (16 tiles of 32x32, BB), 256 threads. Q^T via smem tile transpose.
// ---------------------------------------------------------------------------
__global__ void __launch_bounds__(256) finalize(float* __restrict__ out) {
    __shared__ float qt[32][33];
    const int b = blockIdx.y;
    const int t = blockIdx.x;
    const int tr = (t >> 2) * 32;       // tile row base
    const int tc = (t & 3) * 32;        // tile col base
    const int tid = threadIdx.x;
    const int rl = tid >> 3;            // 0..31 row within tile
    const int cs = (tid & 7) * 4;       // col seg within tile

    const float inv = 1.0f / (float)MM;
    const size_t base = (size_t)b * CC * CC;
    const float* P0 = g_partP + base;
    const float* P1 = g_partP + (size_t)BB * CC * CC + base;
    const float* Q0 = g_partQ + base;
    const float* Q1 = g_partQ + (size_t)BB * CC * CC + base;

    // load Q tile at (tc, tr) coalesced, sum ks, stage for transpose
    {
        const size_t o = (size_t)(tc + rl) * CC + tr + cs;
        const float4 a = *reinterpret_cast<const float4*>(Q0 + o);
        const float4 c = *reinterpret_cast<const float4*>(Q1 + o);
        qt[rl][cs + 0] = a.x + c.x;
        qt[rl][cs + 1] = a.y + c.y;
        qt[rl][cs + 2] = a.z + c.z;
        qt[rl][cs + 3] = a.w + c.w;
    }
    __syncthreads();

    const int r = tr + rl;
    const int c = tc + cs;
    const size_t o = (size_t)r * CC + c;
    const float4 p0 = *reinterpret_cast<const float4*>(P0 + o);
    const float4 p1 = *reinterpret_cast<const float4*>(P1 + o);
    const float4 q0 = *reinterpret_cast<const float4*>(Q0 + o);
    const float4 q1 = *reinterpret_cast<const float4*>(Q1 + o);

    const float mur = (g_sum[b * CC + r] + g_sum[BB * CC + b * CC + r]) * inv;
    const float mc0 = (g_sum[b * CC + c + 0] + g_sum[BB * CC + b * CC + c + 0]) * inv;
    const float mc1 = (g_sum[b * CC + c + 1] + g_sum[BB * CC + b * CC + c + 1]) * inv;
    const float mc2 = (g_sum[b * CC + c + 2] + g_sum[BB * CC + b * CC + c + 2]) * inv;
    const float mc3 = (g_sum[b * CC + c + 3] + g_sum[BB * CC + b * CC + c + 3]) * inv;

    float4 res;
    res.x = (p0.x + p1.x + q0.x + q1.x + qt[cs + 0][rl]) * inv - mur * mc0;
    res.y = (p0.y + p1.y + q0.y + q1.y + qt[cs + 1][rl]) * inv - mur * mc1;
    res.z = (p0.z + p1.z + q0.z + q1.z + qt[cs + 2][rl]) * inv - mur * mc2;
    res.w = (p0.w + p1.w + q0.w + q1.w + qt[cs + 3][rl]) * inv - mur * mc3;
    *reinterpret_cast<float4*>(out + base + o) = res;
}

// ---------------------------------------------------------------------------
extern "C" void kernel_launch(void* const* d_in, const int* in_sizes, int n_in,
                              void* d_out, int out_size) {
    const float* x = (const float*)d_in[0];
    float* out = (float*)d_out;

    dim3 grid(KS, BB);
    syrk_mma<<<grid, 256>>>(x);
    finalize<<<dim3(16, BB), 256>>>(out);
}

// round 7
// speedup vs baseline: 3.9142x; 1.0925x over previous
#include <cuda_runtime.h>
#include <cstdint>

// Problem constants: B=64, C=128, M=H*W=4096, fp32 in/out
#define BB 64
#define CC 128
#define MM 4096
#define KS 2                    // split-K across CTAs
#define KCHUNK (MM / KS)        // 2048
#define KTILE 32                // bf16 k per stage
#define NSTAGE (KCHUNK / KTILE) // 64
#define PITCH 80                // smem row pitch bytes (64B data + 16B pad)
#define TILEB (CC * PITCH)      // 10240 bytes per bf16 tile
#define SPITCH 72               // transpose buffer pitch (floats)

// ---------------- scratch (__device__ globals; no allocs allowed) ----------
__device__ float g_sum[KS * BB * CC];            // per-(ks,b,c) row sums
__device__ float g_part[KS * BB * CC * CC];      // per-ks S = P + Q + Q^T

// ---------------- helpers ---------------------------------------------------
__device__ __forceinline__ uint32_t smem_u32(const void* p) {
    uint32_t a;
    asm("{ .reg .u64 t; cvta.to.shared.u64 t, %1; cvt.u32.u64 %0, t; }"
        : "=r"(a) : "l"(p));
    return a;
}
__device__ __forceinline__ void ldsm_x4(uint32_t& r0, uint32_t& r1,
                                        uint32_t& r2, uint32_t& r3, uint32_t a) {
    asm volatile("ldmatrix.sync.aligned.m8n8.x4.shared.b16 {%0,%1,%2,%3}, [%4];"
                 : "=r"(r0), "=r"(r1), "=r"(r2), "=r"(r3) : "r"(a));
}
__device__ __forceinline__ void mma_bf16(float* d, const uint32_t* a,
                                         uint32_t b0, uint32_t b1) {
    asm volatile(
        "mma.sync.aligned.m16n8k16.row.col.f32.bf16.bf16.f32 "
        "{%0,%1,%2,%3}, {%4,%5,%6,%7}, {%8,%9}, {%0,%1,%2,%3};"
        : "+f"(d[0]), "+f"(d[1]), "+f"(d[2]), "+f"(d[3])
        : "r"(a[0]), "r"(a[1]), "r"(a[2]), "r"(a[3]), "r"(b0), "r"(b1));
}

// ---------------------------------------------------------------------------
// SYRK via bf16-split mma.sync, two-term (P = hi*hi^T, Q = hi*lo^T), with the
// Q + Q^T fold done in-CTA through an smem transpose. grid = (KS, BB).
// ---------------------------------------------------------------------------
__global__ void __launch_bounds__(256, 1) syrk_mma(const float* __restrict__ x) {
    __shared__ __align__(128) union {
        uint8_t tiles[2][2 * TILEB];        // 40960 B: hi/lo double-buffered
        float S[CC][SPITCH];                // 36864 B: Q-transpose staging
    } sm;

    const int tid = threadIdx.x;
    const int wid = tid >> 5;
    const int lid = tid & 31;
    const int b = blockIdx.y;
    const int ks = blockIdx.x;
    const float* xb = x + (size_t)b * CC * MM + ks * KCHUNK;

    const int rw = (wid >> 1) * 32;   // warp row base in 128x128 output
    const int cw = (wid & 1) * 64;    // warp col base

    float accP[2][8][4], accQ[2][8][4];
    #pragma unroll
    for (int mb = 0; mb < 2; mb++)
        #pragma unroll
        for (int jb = 0; jb < 8; jb++)
            #pragma unroll
            for (int q = 0; q < 4; q++) { accP[mb][jb][q] = 0.0f; accQ[mb][jb][q] = 0.0f; }

    float rs[4] = {0.f, 0.f, 0.f, 0.f};

    // loader mapping: thread covers rows it*32 + (tid>>3), k-seg (tid&7)*4
    const int lrow = tid >> 3;
    const int kseg = tid & 7;

    // ldmatrix lane byte-offsets inside a tile
    // A x4: row = base + (l&7) + ((l>>3)&1)*8 ; k-col8 = (l>>4)
    const uint32_t a_row_off = ((lid & 7) + ((lid >> 3) & 1) * 8) * PITCH
                             + ((lid >> 4) * 8) * 2;
    // B x4 (n16 x k16): row = base + (l&7) + (l>>4)*8 ; k-col8 = ((l>>3)&1)
    const uint32_t b4_row_off = ((lid & 7) + (lid >> 4) * 8) * PITCH
                              + (((lid >> 3) & 1) * 8) * 2;

    float4 v[4];
    #pragma unroll
    for (int it = 0; it < 4; it++)
        v[it] = *reinterpret_cast<const float4*>(
            xb + (size_t)(it * 32 + lrow) * MM + kseg * 4);

    for (int s = 0; s < NSTAGE; s++) {
        const int buf = s & 1;
        const uint32_t hibase = smem_u32(&sm.tiles[buf][0]);
        const uint32_t lobase = hibase + TILEB;

        // convert current regs -> smem tiles, accumulate row sums
        #pragma unroll
        for (int it = 0; it < 4; it++) {
            const int row = it * 32 + lrow;
            const float4 xv = v[it];
            rs[it] += (xv.x + xv.y) + (xv.z + xv.w);
            uint32_t h01, h23, l01, l23;
            asm("cvt.rn.bf16x2.f32 %0, %1, %2;" : "=r"(h01) : "f"(xv.y), "f"(xv.x));
            asm("cvt.rn.bf16x2.f32 %0, %1, %2;" : "=r"(h23) : "f"(xv.w), "f"(xv.z));
            const float hx = __uint_as_float(h01 << 16);
            const float hy = __uint_as_float(h01 & 0xffff0000u);
            const float hz = __uint_as_float(h23 << 16);
            const float hw = __uint_as_float(h23 & 0xffff0000u);
            asm("cvt.rn.bf16x2.f32 %0, %1, %2;" : "=r"(l01) : "f"(xv.y - hy), "f"(xv.x - hx));
            asm("cvt.rn.bf16x2.f32 %0, %1, %2;" : "=r"(l23) : "f"(xv.w - hw), "f"(xv.z - hz));
            const uint32_t off = row * PITCH + kseg * 8;
            asm volatile("st.shared.v2.b32 [%0], {%1,%2};"
                         :: "r"(hibase + off), "r"(h01), "r"(h23));
            asm volatile("st.shared.v2.b32 [%0], {%1,%2};"
                         :: "r"(lobase + off), "r"(l01), "r"(l23));
        }
        // Single barrier per stage (double buffering covers the WAR hazard).
        __syncthreads();

        // issue next stage's global loads early (latency hidden by MMA work)
        if (s + 1 < NSTAGE) {
            const int k0 = (s + 1) * KTILE;
            #pragma unroll
            for (int it = 0; it < 4; it++)
                v[it] = *reinterpret_cast<const float4*>(
                    xb + (size_t)(it * 32 + lrow) * MM + k0 + kseg * 4);
        }

        // compute: 2 k16 steps; A is always hi; B fragments via x4 (n16 each)
        #pragma unroll
        for (int kb = 0; kb < 2; kb++) {
            uint32_t ah[2][4];
            #pragma unroll
            for (int mb = 0; mb < 2; mb++) {
                const uint32_t aoff = (rw + mb * 16) * PITCH + kb * 32 + a_row_off;
                ldsm_x4(ah[mb][0], ah[mb][1], ah[mb][2], ah[mb][3], hibase + aoff);
            }
            #pragma unroll
            for (int jbp = 0; jbp < 4; jbp++) {
                const uint32_t boff = (cw + jbp * 16) * PITCH + kb * 32 + b4_row_off;
                uint32_t bh0, bh1, bh2, bh3, bl0, bl1, bl2, bl3;
                ldsm_x4(bh0, bh1, bh2, bh3, hibase + boff);
                ldsm_x4(bl0, bl1, bl2, bl3, lobase + boff);
                #pragma unroll
                for (int mb = 0; mb < 2; mb++) {
                    mma_bf16(accP[mb][2 * jbp + 0], ah[mb], bh0, bh1);
                    mma_bf16(accP[mb][2 * jbp + 1], ah[mb], bh2, bh3);
                    mma_bf16(accQ[mb][2 * jbp + 0], ah[mb], bl0, bl1);
                    mma_bf16(accQ[mb][2 * jbp + 1], ah[mb], bl2, bl3);
                }
            }
        }
    }

    // row sums: 8 lanes (same tid>>3 group) share a row; plain store per ks
    #pragma unroll
    for (int it = 0; it < 4; it++) {
        float vv = rs[it];
        vv += __shfl_xor_sync(0xffffffffu, vv, 4);
        vv += __shfl_xor_sync(0xffffffffu, vv, 2);
        vv += __shfl_xor_sync(0xffffffffu, vv, 1);
        if ((lid & 7) == 0)
            g_sum[ks * BB * CC + b * CC + it * 32 + lrow] = vv;
    }

    // ---- Q + Q^T fold via smem transpose (2 column-half phases) ------------
    const int g = lid >> 2;            // 0..7
    const int tg = lid & 3;            // 0..3
    __syncthreads();                   // last-stage ldsm done before S overlay
    #pragma unroll
    for (int h = 0; h < 2; h++) {
        // producers: warps whose column half == h store their accQ
        if ((wid & 1) == h) {
            #pragma unroll
            for (int mb = 0; mb < 2; mb++)
                #pragma unroll
                for (int jb = 0; jb < 8; jb++) {
                    const int row = rw + mb * 16 + g;
                    const int cl = jb * 8 + tg * 2;
                    sm.S[row][cl]         = accQ[mb][jb][0];
                    sm.S[row][cl + 1]     = accQ[mb][jb][1];
                    sm.S[row + 8][cl]     = accQ[mb][jb][2];
                    sm.S[row + 8][cl + 1] = accQ[mb][jb][3];
                }
        }
        __syncthreads();
        // consumers: warps whose rows lie in [h*64, h*64+64) add Q^T
        if ((wid >> 2) == h) {
            #pragma unroll
            for (int mb = 0; mb < 2; mb++)
                #pragma unroll
                for (int jb = 0; jb < 8; jb++) {
                    const int C = cw + jb * 8 + tg * 2;
                    const int R0 = (rw + mb * 16 + g) & 63;
                    accP[mb][jb][0] += sm.S[C][R0];
                    accP[mb][jb][1] += sm.S[C + 1][R0];
                    accP[mb][jb][2] += sm.S[C][R0 + 8];
                    accP[mb][jb][3] += sm.S[C + 1][R0 + 8];
                }
        }
        __syncthreads();
    }

    // epilogue: write S = P + Q^T(accumulated) + Q
    float* dst = g_part + (size_t)(ks * BB + b) * (CC * CC);
    #pragma unroll
    for (int mb = 0; mb < 2; mb++) {
        #pragma unroll
        for (int jb = 0; jb < 8; jb++) {
            const int row = rw + mb * 16 + g;
            const int col = cw + jb * 8 + tg * 2;
            *reinterpret_cast<float2*>(&dst[(size_t)row * CC + col]) =
                make_float2(accP[mb][jb][0] + accQ[mb][jb][0],
                            accP[mb][jb][1] + accQ[mb][jb][1]);
            *reinterpret_cast<float2*>(&dst[(size_t)(row + 8) * CC + col]) =
                make_float2(accP[mb][jb][2] + accQ[mb][jb][2],
                            accP[mb][jb][3] + accQ[mb][jb][3]);
        }
    }
}

// ---------------------------------------------------------------------------
// out[b][r][c] = (S0 + S1)/M - mu_r * mu_c
// ---------------------------------------------------------------------------
__global__ void __launch_bounds__(256) finalize(float* __restrict__ out) {
    const int i = blockIdx.x * blockDim.x + threadIdx.x;    // float4 index
    const int base = i * 4;
    const int b = base >> 14;
    const int r = (base >> 7) & (CC - 1);
    const int c = base & (CC - 1);
    const float inv = 1.0f / (float)MM;

    const float4 s0 = reinterpret_cast<const float4*>(g_part)[i];
    const float4 s1 = reinterpret_cast<const float4*>(g_part)[BB * CC * CC / 4 + i];

    const float mur = (g_sum[b * CC + r] + g_sum[BB * CC + b * CC + r]) * inv;
    const float mc0 = (g_sum[b * CC + c + 0] + g_sum[BB * CC + b * CC + c + 0]) * inv;
    const float mc1 = (g_sum[b * CC + c + 1] + g_sum[BB * CC + b * CC + c + 1]) * inv;
    const float mc2 = (g_sum[b * CC + c + 2] + g_sum[BB * CC + b * CC + c + 2]) * inv;
    const float mc3 = (g_sum[b * CC + c + 3] + g_sum[BB * CC + b * CC + c + 3]) * inv;

    float4 o;
    o.x = (s0.x + s1.x) * inv - mur * mc0;
    o.y = (s0.y + s1.y) * inv - mur * mc1;
    o.z = (s0.z + s1.z) * inv - mur * mc2;
    o.w = (s0.w + s1.w) * inv - mur * mc3;
    reinterpret_cast<float4*>(out)[i] = o;
}

// ---------------------------------------------------------------------------
extern "C" void kernel_launch(void* const* d_in, const int* in_sizes, int n_in,
                              void* d_out, int out_size) {
    const float* x = (const float*)d_in[0];
    float* out = (float*)d_out;

    dim3 grid(KS, BB);
    syrk_mma<<<grid, 256>>>(x);
    finalize<<<(BB * CC * CC / 4) / 256, 256>>>(out);
}